// round 14
// baseline (speedup 1.0000x reference)
#include <cuda_runtime.h>
#include <cstdint>

#define B_ 2
#define S_ 1024
#define D_ 128

typedef unsigned long long u64;

// ---------------- scratch ----------------
__device__ float g_Qt[B_*D_*S_];     // q' = 1-Q, transposed [b][d][s]
__device__ float g_Kt[B_*D_*S_];     // k' = 1-K, transposed [b][d][s]
__device__ float g_sumK[B_*S_];      // 128 - sum_d k' per row
__device__ float g_V[B_*S_*D_];      // V [b][s][d]
__device__ float g_Z[B_*S_];         // row sums of E' = exp(10T)-1
__device__ float g_totVp[128*128];   // per-qkv-block partial sums of V

__device__ __forceinline__ u64 pack2(float a, float b){
  u64 r; asm("mov.b64 %0, {%1, %2};" : "=l"(r) : "f"(a), "f"(b)); return r;
}
__device__ __forceinline__ void unpack2(u64 v, float& a, float& b){
  asm("mov.b64 {%0, %1}, %2;" : "=f"(a), "=f"(b) : "l"(v));
}
__device__ __forceinline__ u64 fma2(u64 a, u64 b, u64 c){
  u64 d; asm("fma.rn.f32x2 %0, %1, %2, %3;" : "=l"(d) : "l"(a), "l"(b), "l"(c)); return d;
}
__device__ __forceinline__ unsigned su32(const void* p){
  return (unsigned)__cvta_generic_to_shared(p);
}
#define CP16(s,g) asm volatile("cp.async.cg.shared.global [%0], [%1], 16;" :: "r"(s), "l"(g) : "memory")
#define CPC()  asm volatile("cp.async.commit_group;" ::: "memory")
#define CPW0() asm volatile("cp.async.wait_group 0;" ::: "memory")

// phase-1 compute: 64 (FSET,FFMA) pairs (8q x 8k)
__device__ __forceinline__ void p1c8(float (&acc)[8][8],
    const float4& qa0, const float4& qa1,
    const float4& kf0, const float4& kf1){
  float qq[8] = {qa0.x,qa0.y,qa0.z,qa0.w, qa1.x,qa1.y,qa1.z,qa1.w};
  float kk[8] = {kf0.x,kf0.y,kf0.z,kf0.w, kf1.x,kf1.y,kf1.z,kf1.w};
  #pragma unroll
  for (int i=0;i<8;i++)
    #pragma unroll
    for (int j=0;j<8;j++)
      asm("{.reg .f32 m; set.le.f32.f32 m, %1, %2; fma.rn.f32 %0, m, %1, %0;}"
          : "+f"(acc[i][j]) : "f"(kk[j]), "f"(qq[i]));
}

// k_qkv inner compute (8 rows): 24 fma2 (+3 pack)
__device__ __forceinline__ void qkvc8(u64 (&aq)[8], u64 (&ak)[8], u64 (&av)[8],
                                      const u64* xp, const float* wv6){
  u64 wqp = pack2(wv6[0], wv6[1]);
  u64 wkp = pack2(wv6[2], wv6[3]);
  u64 wvp = pack2(wv6[4], wv6[5]);
  #pragma unroll
  for (int r=0;r<8;r++){
    aq[r] = fma2(wqp, xp[r], aq[r]);
    ak[r] = fma2(wkp, xp[r], ak[r]);
    av[r] = fma2(wvp, xp[r], av[r]);
  }
}

// ---------------- K1: QKV (+ zero out/Z + zero att upper + totV partials)
// 128 blocks x 256 threads, 16 seq rows per block, 8 rows/thread.
__global__ void __launch_bounds__(256,1) k_qkv(
    const float* __restrict__ x,
    const float* __restrict__ wq, const float* __restrict__ bq,
    const float* __restrict__ wk, const float* __restrict__ bk,
    const float* __restrict__ wv, const float* __restrict__ bv,
    float* __restrict__ outp){
  extern __shared__ float sm[];
  float* ws = sm;                 // [2][3][32][128]  = 24576 floats
  float* xs = sm + 24576;         // [16][128]        = 2048 floats
  __shared__ float wred[8][8];    // [warp][row]
  __shared__ float wtot[2][128];

  int t = threadIdx.x;
  int o = t & 127;
  int h = t >> 7;                 // 0..1, 8 rows each
  int s0 = blockIdx.x*16;
  int b  = s0 >> 10;
  int sl = s0 & 1023;

  const float4* wq4 = (const float4*)wq;
  const float4* wk4 = (const float4*)wk;
  const float4* wv4 = (const float4*)wv;
  float4* ws4 = (float4*)ws;
  float4* xs4 = (float4*)xs;

  // stage x tile (512 f4) + weight chunk 0 (3072 f4) via cp.async
  #pragma unroll
  for (int j=0;j<2;j++)
    CP16(su32(&xs4[t + j*256]), &((const float4*)(x + s0*D_))[t + j*256]);
  #pragma unroll
  for (int j=0;j<12;j++){
    int i = t + j*256;
    int m = i >> 10, r = i & 1023;
    const float4* src = (m==0)? wq4 : (m==1)? wk4 : wv4;
    CP16(su32(&ws4[i]), &src[(r>>5)*32 + (r&31)]);
  }
  CPC();

  // overlap: zero out region + g_Z + att upper triangle while staging lands
  #pragma unroll
  for (int j=0;j<2;j++)
    ((float4*)outp)[blockIdx.x*512 + t + j*256] = make_float4(0.f,0.f,0.f,0.f);
  if (t < 16) g_Z[blockIdx.x*16 + t] = 0.f;
  {
    float* att = outp + B_*S_*D_;
    int q0u = sl & ~127;
    int start = q0u + 128;
    if (start < 1024){
      int w4 = (1024 - start) >> 2;      // <= 224
      float4 z4 = make_float4(0.f,0.f,0.f,0.f);
      #pragma unroll
      for (int row=0; row<16; row++){
        if (t < w4)
          ((float4*)(att + (b*S_ + sl + row)*S_ + start))[t] = z4;
      }
    }
  }

  CPW0();
  __syncthreads();

  u64 aq[8], ak[8], av[8];
  #pragma unroll
  for (int jr=0;jr<8;jr++){ aq[jr]=0ull; ak[jr]=0ull; av[jr]=0ull; }

  #pragma unroll 1
  for (int c=0; c<4; c++){
    if (c < 3){
      int f = (c+1)&1;
      #pragma unroll
      for (int j=0;j<12;j++){
        int i = t + j*256;
        int m = i >> 10, r = i & 1023;
        const float4* src = (m==0)? wq4 : (m==1)? wk4 : wv4;
        CP16(su32(&ws4[f*3072 + i]), &src[((c+1)*32 + (r>>5))*32 + (r&31)]);
      }
      CPC();
    }
    const float* wb = ws + (c&1)*12288;
    const float* xb = xs + (h*8)*128 + c*32;

    u64 xp[8]; float wv6[6];
    #pragma unroll
    for (int r=0;r<8;r++) xp[r] = *(const u64*)&xb[r*128];
    wv6[0]=wb[o];        wv6[1]=wb[128+o];
    wv6[2]=wb[4096+o];   wv6[3]=wb[4096+128+o];
    wv6[4]=wb[8192+o];   wv6[5]=wb[8192+128+o];

    #pragma unroll 3
    for (int dp=0; dp<15; dp++){
      int d2 = (dp+1)*2;
      u64 xn[8]; float wn[6];
      #pragma unroll
      for (int r=0;r<8;r++) xn[r] = *(const u64*)&xb[r*128 + d2];
      wn[0]=wb[d2*128+o];        wn[1]=wb[(d2+1)*128+o];
      wn[2]=wb[4096+d2*128+o];   wn[3]=wb[4096+(d2+1)*128+o];
      wn[4]=wb[8192+d2*128+o];   wn[5]=wb[8192+(d2+1)*128+o];
      qkvc8(aq, ak, av, xp, wv6);
      #pragma unroll
      for (int r=0;r<8;r++) xp[r]=xn[r];
      #pragma unroll
      for (int r=0;r<6;r++) wv6[r]=wn[r];
    }
    qkvc8(aq, ak, av, xp, wv6);   // dp = 15
    if (c < 3) CPW0();
    __syncthreads();
  }

  float bqv = bq[o], bkv = bk[o], bvv = bv[o];
  float qv[8], kv[8], vv[8];
  #pragma unroll
  for (int jr=0;jr<8;jr++){
    float a0,a1;
    unpack2(aq[jr],a0,a1); qv[jr] = a0+a1+bqv;
    unpack2(ak[jr],a0,a1); kv[jr] = a0+a1+bkv;
    unpack2(av[jr],a0,a1); vv[jr] = a0+a1+bvv;
  }
  // primes: q' = 1 - sigmoid(z) = 1/(1+exp(z))
  #pragma unroll
  for (int jr=0;jr<8;jr++){
    qv[jr] = 1.f/(1.f+__expf(qv[jr]));
    kv[jr] = 1.f/(1.f+__expf(kv[jr]));
  }

  #pragma unroll
  for (int jr=0;jr<8;jr++) g_V[(s0 + h*8 + jr)*D_ + o] = vv[jr];

  {
    float* qtp = g_Qt + b*D_*S_ + o*S_ + sl + h*8;
    float* ktp = g_Kt + b*D_*S_ + o*S_ + sl + h*8;
    ((float4*)qtp)[0] = make_float4(qv[0],qv[1],qv[2],qv[3]);
    ((float4*)qtp)[1] = make_float4(qv[4],qv[5],qv[6],qv[7]);
    ((float4*)ktp)[0] = make_float4(kv[0],kv[1],kv[2],kv[3]);
    ((float4*)ktp)[1] = make_float4(kv[4],kv[5],kv[6],kv[7]);
  }

  // totV partial for this block
  wtot[h][o] = vv[0]+vv[1]+vv[2]+vv[3]+vv[4]+vv[5]+vv[6]+vv[7];

  // sumK = 128 - sum_d k'  (warp shuffle over o-lanes + cross-warp)
  float red[8];
  #pragma unroll
  for (int jr=0;jr<8;jr++) red[jr] = kv[jr];
  #pragma unroll
  for (int off=16; off>=1; off>>=1){
    #pragma unroll
    for (int jr=0;jr<8;jr++) red[jr] += __shfl_xor_sync(0xffffffffu, red[jr], off);
  }
  int w = t >> 5;                 // 0..7
  if ((t & 31) == 0){
    #pragma unroll
    for (int jr=0;jr<8;jr++) wred[w][jr] = red[jr];
  }
  __syncthreads();
  if (t < 16){
    int r = t;                    // row 0..15
    int hh = r >> 3, jr = r & 7;  // h group, row-within
    float tot = wred[hh*4+0][jr]+wred[hh*4+1][jr]+wred[hh*4+2][jr]+wred[hh*4+3][jr];
    g_sumK[s0 + r] = 128.f - tot;
  }
  if (t < 128)
    g_totVp[blockIdx.x*128 + t] = wtot[0][t]+wtot[1][t];
}

// ---------------- K2: fused truth + E' + Z + E'@V ------------------------
// 144 blocks x 128 threads (4 warps, 1/SMSP): 128q x 64k tiles, fat threads.
__global__ void __launch_bounds__(128,1) k_main(float* __restrict__ outp){
  extern __shared__ float sm[];
  float* Qts = sm;                 // [128 d][128 q] 16384 fl -> reused as Vs
  float* Kts = sm + 16384;         // [128 d][64 k]   8192 fl -> reused as Es
  float* sKs = sm + 24576;         // [64]
  float* Es  = sm + 16384;         // [64 k][pitch 132] 8448 fl
  float* Vs  = sm;                 // [64 k][128 d]     8192 fl
  int bid = blockIdx.x;
  int t = threadIdx.x;
  float* att = outp + B_*S_*D_;

  int b = bid/72, r = bid - b*72;
  int qt = 0;
  while ((qt+1)*(qt+2) <= r) qt++;
  int k0 = (r - qt*(qt+1))*64;
  int q0 = qt*128;
  int tx = t & 7, ty = t >> 3;     // ty 0..15 (8 q each), tx 0..7 (8 k each)

  const float4* Qg = (const float4*)(g_Qt + b*D_*S_);
  const float4* Kg = (const float4*)(g_Kt + b*D_*S_);
  const float4* Vg = (const float4*)(g_V + b*S_*D_);

  float4* Qts4 = (float4*)Qts;
  float4* Kts4 = (float4*)Kts;

  // stage Q + K + sKs via cp.async
  #pragma unroll
  for (int it=0; it<32; it++){
    int i = t + it*128;                     // 4096 f4
    CP16(su32(&Qts4[i]), &Qg[(i>>5)*256 + (q0>>2) + (i&31)]);
  }
  #pragma unroll
  for (int it=0; it<16; it++){
    int i = t + it*128;                     // 2048 f4
    CP16(su32(&Kts4[i]), &Kg[(i>>4)*256 + (k0>>2) + (i&15)]);
  }
  if (t < 16)
    CP16(su32(&sKs[t*4]), (const float4*)&g_sumK[b*S_ + k0 + t*4]);
  CPC();
  CPW0();
  __syncthreads();

  // phase 1: acc = sum_d [k' <= q'] * k'   (8q x 8k, prefetch d+1)
  float acc[8][8];
  #pragma unroll
  for (int i=0;i<8;i++)
    #pragma unroll
    for (int j=0;j<8;j++) acc[i][j] = 0.f;

  {
    float4 qa0 = Qts4[ty*2],      qa1 = Qts4[ty*2+1];
    float4 kf0 = Kts4[tx*2],      kf1 = Kts4[tx*2+1];
    #pragma unroll 2
    for (int d=0; d<127; d++){
      float4 qn0 = Qts4[(d+1)*32 + ty*2];
      float4 qn1 = Qts4[(d+1)*32 + ty*2 + 1];
      float4 kn0 = Kts4[(d+1)*16 + tx*2];
      float4 kn1 = Kts4[(d+1)*16 + tx*2 + 1];
      p1c8(acc, qa0, qa1, kf0, kf1);
      qa0=qn0; qa1=qn1; kf0=kn0; kf1=kn1;
    }
    p1c8(acc, qa0, qa1, kf0, kf1);          // d = 127
  }

  // phase 2: T, att store, E' = exp(10T)-1 (overwrites acc), Z partial
  const float inv = 1.f/128.f;
  float sk[8];
  {
    float4 s0v = ((const float4*)&sKs[tx*8])[0];
    float4 s1v = ((const float4*)&sKs[tx*8])[1];
    sk[0]=s0v.x; sk[1]=s0v.y; sk[2]=s0v.z; sk[3]=s0v.w;
    sk[4]=s1v.x; sk[5]=s1v.y; sk[6]=s1v.z; sk[7]=s1v.w;
  }
  #pragma unroll
  for (int i=0;i<8;i++){
    int qg = q0 + ty*8 + i;
    float zrow = 0.f;
    float tt[8];
    #pragma unroll
    for (int j=0;j<8;j++){
      int kg = k0 + tx*8 + j;
      float T = (acc[i][j] + sk[j]) * inv;
      bool val = (kg <= qg);
      T = val ? T : 0.f;
      float ee = val ? (__expf(10.f*T) - 1.f) : 0.f;
      tt[j] = T; acc[i][j] = ee; zrow += ee;
    }
    float* ap = att + (b*S_ + qg)*S_ + k0 + tx*8;
    ((float4*)ap)[0] = make_float4(tt[0],tt[1],tt[2],tt[3]);
    ((float4*)ap)[1] = make_float4(tt[4],tt[5],tt[6],tt[7]);
    #pragma unroll
    for (int off=4; off>=1; off>>=1)
      zrow += __shfl_xor_sync(0xffffffffu, zrow, off);
    if (tx == 0) atomicAdd(&g_Z[b*S_ + qg], zrow);
  }
  __syncthreads();     // all reads of Qts/Kts/sKs done

  // phase 3: V tile via cp.async (latency overlapped with E' staging)
  float4* Vs4 = (float4*)Vs;
  #pragma unroll
  for (int it=0; it<16; it++){
    int i = t + it*128;                     // 2048 f4
    CP16(su32(&Vs4[i]), &Vg[(k0 + (i>>5))*32 + (i&31)]);
  }
  CPC();
  // stage E' (k-major, pitch 132, tx-rotated store order)
  #pragma unroll
  for (int jj=0;jj<8;jj++){
    int j = (jj + tx) & 7;                  // rotation kills bank conflicts
    int kl = tx*8 + j;
    float* ep = Es + kl*132 + ty*8;
    ((float4*)ep)[0] = make_float4(acc[0][j],acc[1][j],acc[2][j],acc[3][j]);
    ((float4*)ep)[1] = make_float4(acc[4][j],acc[5][j],acc[6][j],acc[7][j]);
  }
  CPW0();
  __syncthreads();

  // phase 4: out += E'^T @ V   (8q x 32d per thread, f32x2)
  u64 acc2[8][8];
  #pragma unroll
  for (int i=0;i<8;i++)
    #pragma unroll
    for (int j=0;j<8;j++) acc2[i][j] = 0ull;

  #pragma unroll 2
  for (int k=0;k<64;k++){
    float4 e0 = ((const float4*)&Es[k*132 + ty*8])[0];
    float4 e1 = ((const float4*)&Es[k*132 + ty*8])[1];
    float ev[8] = {e0.x,e0.y,e0.z,e0.w, e1.x,e1.y,e1.z,e1.w};
    u64 v[8];
    #pragma unroll
    for (int c=0;c<4;c++){
      float4 vv4 = Vs4[k*32 + tx + 8*c];    // conflict-free
      v[2*c]   = pack2(vv4.x, vv4.y);
      v[2*c+1] = pack2(vv4.z, vv4.w);
    }
    #pragma unroll
    for (int i=0;i<8;i++){
      u64 e2 = pack2(ev[i], ev[i]);
      #pragma unroll
      for (int j=0;j<8;j++)
        acc2[i][j] = fma2(e2, v[j], acc2[i][j]);
    }
  }

  #pragma unroll
  for (int i=0;i<8;i++){
    int qg = q0 + ty*8 + i;
    float* op = outp + (b*S_ + qg)*D_;
    #pragma unroll
    for (int c=0;c<4;c++){
      float a0,a1,a2,a3;
      unpack2(acc2[i][2*c],   a0,a1);
      unpack2(acc2[i][2*c+1], a2,a3);
      atomicAdd((float4*)(op + (tx + 8*c)*4), make_float4(a0,a1,a2,a3));
    }
  }
}

// ---------------- K3: out = (out + totV) / (Z + 1024) --------------------
__global__ void __launch_bounds__(256) k_norm(float* __restrict__ outp){
  __shared__ float4 stot[64];
  int t = threadIdx.x;
  {
    int ft = t >> 2, p = t & 3;
    int rb = ft >> 5, col = ft & 31;
    const float4* tp = (const float4*)g_totVp;
    float4 a = make_float4(0.f,0.f,0.f,0.f);
    #pragma unroll 4
    for (int j = p*16; j < p*16+16; j++){
      float4 v = tp[(rb*64 + j)*32 + col];
      a.x+=v.x; a.y+=v.y; a.z+=v.z; a.w+=v.w;
    }
    #pragma unroll
    for (int off=1; off<4; off<<=1){
      a.x += __shfl_xor_sync(0xffffffffu, a.x, off);
      a.y += __shfl_xor_sync(0xffffffffu, a.y, off);
      a.z += __shfl_xor_sync(0xffffffffu, a.z, off);
      a.w += __shfl_xor_sync(0xffffffffu, a.w, off);
    }
    if (p == 0) stot[ft] = a;
  }
  __syncthreads();

  int col = t & 31;
  float4* o4 = (float4*)outp;
  #pragma unroll
  for (int rr=0; rr<2; rr++){
    int row = blockIdx.x*16 + (t>>5) + rr*8;
    float4 v = o4[row*32 + col];
    float4 tv = stot[((row >> 10) << 5) + col];
    float rz = 1.f/(g_Z[row] + 1024.f);
    v.x=(v.x+tv.x)*rz; v.y=(v.y+tv.y)*rz;
    v.z=(v.z+tv.z)*rz; v.w=(v.w+tv.w)*rz;
    o4[row*32 + col] = v;
  }
}

// ---------------- launch ----------------
extern "C" void kernel_launch(void* const* d_in, const int* in_sizes, int n_in,
                              void* d_out, int out_size){
  (void)in_sizes; (void)n_in; (void)out_size;
  const float* x  = (const float*)d_in[0];
  const float* wq = (const float*)d_in[1];
  const float* bq = (const float*)d_in[2];
  const float* wk = (const float*)d_in[3];
  const float* bk = (const float*)d_in[4];
  const float* wv = (const float*)d_in[5];
  const float* bv = (const float*)d_in[6];
  float* out = (float*)d_out;              // (output, attention_truth)

  const int SMQ = (24576 + 2048) * 4;      // 106,496 B
  const int SMM = 24832 * 4;               // 99,328 B
  cudaFuncSetAttribute(k_qkv,  cudaFuncAttributeMaxDynamicSharedMemorySize, SMQ);
  cudaFuncSetAttribute(k_main, cudaFuncAttributeMaxDynamicSharedMemorySize, SMM);

  k_qkv  <<< 128, 256, SMQ >>>(x, wq, bq, wk, bk, wv, bv, out);
  k_main <<< 144, 128, SMM >>>(out);
  k_norm <<< 128, 256 >>>(out);
}

// round 15
// speedup vs baseline: 1.0330x; 1.0330x over previous
#include <cuda_runtime.h>
#include <cstdint>

#define B_ 2
#define S_ 1024
#define D_ 128

typedef unsigned long long u64;

// ---------------- scratch ----------------
__device__ float g_Qt[B_*D_*S_];     // q' = 1-Q, transposed [b][d][s]
__device__ float g_Kt[B_*D_*S_];     // k' = 1-K, transposed [b][d][s]
__device__ float g_sumK[B_*S_];      // 128 - sum_d k' per row
__device__ float g_V[B_*S_*D_];      // V [b][s][d]
__device__ float g_Z[B_*S_];         // row sums of E' = exp(10T)-1
__device__ float g_totVp[128*128];   // per-qkv-block partial sums of V

__device__ __forceinline__ u64 pack2(float a, float b){
  u64 r; asm("mov.b64 %0, {%1, %2};" : "=l"(r) : "f"(a), "f"(b)); return r;
}
__device__ __forceinline__ void unpack2(u64 v, float& a, float& b){
  asm("mov.b64 {%0, %1}, %2;" : "=f"(a), "=f"(b) : "l"(v));
}
__device__ __forceinline__ u64 fma2(u64 a, u64 b, u64 c){
  u64 d; asm("fma.rn.f32x2 %0, %1, %2, %3;" : "=l"(d) : "l"(a), "l"(b), "l"(c)); return d;
}
__device__ __forceinline__ unsigned su32(const void* p){
  return (unsigned)__cvta_generic_to_shared(p);
}
#define CP16(s,g) asm volatile("cp.async.cg.shared.global [%0], [%1], 16;" :: "r"(s), "l"(g) : "memory")
#define CPC()  asm volatile("cp.async.commit_group;" ::: "memory")
#define CPW0() asm volatile("cp.async.wait_group 0;" ::: "memory")

// phase-1 compute: 32 (FSET,FFMA) pairs (8q x 4k)
__device__ __forceinline__ void p1c84(float (&acc)[8][4],
    const float4& qa0, const float4& qa1, const float4& kf){
  float qq[8] = {qa0.x,qa0.y,qa0.z,qa0.w, qa1.x,qa1.y,qa1.z,qa1.w};
  float kk[4] = {kf.x,kf.y,kf.z,kf.w};
  #pragma unroll
  for (int i=0;i<8;i++)
    #pragma unroll
    for (int j=0;j<4;j++)
      asm("{.reg .f32 m; set.le.f32.f32 m, %1, %2; fma.rn.f32 %0, m, %1, %0;}"
          : "+f"(acc[i][j]) : "f"(kk[j]), "f"(qq[i]));
}

// k_qkv inner compute (8 rows): 24 fma2 (+3 pack)
__device__ __forceinline__ void qkvc8(u64 (&aq)[8], u64 (&ak)[8], u64 (&av)[8],
                                      const u64* xp, const float* wv6){
  u64 wqp = pack2(wv6[0], wv6[1]);
  u64 wkp = pack2(wv6[2], wv6[3]);
  u64 wvp = pack2(wv6[4], wv6[5]);
  #pragma unroll
  for (int r=0;r<8;r++){
    aq[r] = fma2(wqp, xp[r], aq[r]);
    ak[r] = fma2(wkp, xp[r], ak[r]);
    av[r] = fma2(wvp, xp[r], av[r]);
  }
}

// ---------------- K1: QKV (+ zero out/Z + zero att upper + totV partials)
// 128 blocks x 256 threads, 16 seq rows per block, 8 rows/thread. (frozen)
__global__ void __launch_bounds__(256,1) k_qkv(
    const float* __restrict__ x,
    const float* __restrict__ wq, const float* __restrict__ bq,
    const float* __restrict__ wk, const float* __restrict__ bk,
    const float* __restrict__ wv, const float* __restrict__ bv,
    float* __restrict__ outp){
  extern __shared__ float sm[];
  float* ws = sm;                 // [2][3][32][128]  = 24576 floats
  float* xs = sm + 24576;         // [16][128]        = 2048 floats
  __shared__ float wred[8][8];    // [warp][row]
  __shared__ float wtot[2][128];

  int t = threadIdx.x;
  int o = t & 127;
  int h = t >> 7;                 // 0..1, 8 rows each
  int s0 = blockIdx.x*16;
  int b  = s0 >> 10;
  int sl = s0 & 1023;

  const float4* wq4 = (const float4*)wq;
  const float4* wk4 = (const float4*)wk;
  const float4* wv4 = (const float4*)wv;
  float4* ws4 = (float4*)ws;
  float4* xs4 = (float4*)xs;

  #pragma unroll
  for (int j=0;j<2;j++)
    CP16(su32(&xs4[t + j*256]), &((const float4*)(x + s0*D_))[t + j*256]);
  #pragma unroll
  for (int j=0;j<12;j++){
    int i = t + j*256;
    int m = i >> 10, r = i & 1023;
    const float4* src = (m==0)? wq4 : (m==1)? wk4 : wv4;
    CP16(su32(&ws4[i]), &src[(r>>5)*32 + (r&31)]);
  }
  CPC();

  #pragma unroll
  for (int j=0;j<2;j++)
    ((float4*)outp)[blockIdx.x*512 + t + j*256] = make_float4(0.f,0.f,0.f,0.f);
  if (t < 16) g_Z[blockIdx.x*16 + t] = 0.f;
  {
    float* att = outp + B_*S_*D_;
    int q0u = sl & ~127;
    int start = q0u + 128;
    if (start < 1024){
      int w4 = (1024 - start) >> 2;      // <= 224
      float4 z4 = make_float4(0.f,0.f,0.f,0.f);
      #pragma unroll
      for (int row=0; row<16; row++){
        if (t < w4)
          ((float4*)(att + (b*S_ + sl + row)*S_ + start))[t] = z4;
      }
    }
  }

  CPW0();
  __syncthreads();

  u64 aq[8], ak[8], av[8];
  #pragma unroll
  for (int jr=0;jr<8;jr++){ aq[jr]=0ull; ak[jr]=0ull; av[jr]=0ull; }

  #pragma unroll 1
  for (int c=0; c<4; c++){
    if (c < 3){
      int f = (c+1)&1;
      #pragma unroll
      for (int j=0;j<12;j++){
        int i = t + j*256;
        int m = i >> 10, r = i & 1023;
        const float4* src = (m==0)? wq4 : (m==1)? wk4 : wv4;
        CP16(su32(&ws4[f*3072 + i]), &src[((c+1)*32 + (r>>5))*32 + (r&31)]);
      }
      CPC();
    }
    const float* wb = ws + (c&1)*12288;
    const float* xb = xs + (h*8)*128 + c*32;

    u64 xp[8]; float wv6[6];
    #pragma unroll
    for (int r=0;r<8;r++) xp[r] = *(const u64*)&xb[r*128];
    wv6[0]=wb[o];        wv6[1]=wb[128+o];
    wv6[2]=wb[4096+o];   wv6[3]=wb[4096+128+o];
    wv6[4]=wb[8192+o];   wv6[5]=wb[8192+128+o];

    #pragma unroll 3
    for (int dp=0; dp<15; dp++){
      int d2 = (dp+1)*2;
      u64 xn[8]; float wn[6];
      #pragma unroll
      for (int r=0;r<8;r++) xn[r] = *(const u64*)&xb[r*128 + d2];
      wn[0]=wb[d2*128+o];        wn[1]=wb[(d2+1)*128+o];
      wn[2]=wb[4096+d2*128+o];   wn[3]=wb[4096+(d2+1)*128+o];
      wn[4]=wb[8192+d2*128+o];   wn[5]=wb[8192+(d2+1)*128+o];
      qkvc8(aq, ak, av, xp, wv6);
      #pragma unroll
      for (int r=0;r<8;r++) xp[r]=xn[r];
      #pragma unroll
      for (int r=0;r<6;r++) wv6[r]=wn[r];
    }
    qkvc8(aq, ak, av, xp, wv6);   // dp = 15
    if (c < 3) CPW0();
    __syncthreads();
  }

  float bqv = bq[o], bkv = bk[o], bvv = bv[o];
  float qv[8], kv[8], vv[8];
  #pragma unroll
  for (int jr=0;jr<8;jr++){
    float a0,a1;
    unpack2(aq[jr],a0,a1); qv[jr] = a0+a1+bqv;
    unpack2(ak[jr],a0,a1); kv[jr] = a0+a1+bkv;
    unpack2(av[jr],a0,a1); vv[jr] = a0+a1+bvv;
  }
  #pragma unroll
  for (int jr=0;jr<8;jr++){
    qv[jr] = 1.f/(1.f+__expf(qv[jr]));
    kv[jr] = 1.f/(1.f+__expf(kv[jr]));
  }

  #pragma unroll
  for (int jr=0;jr<8;jr++) g_V[(s0 + h*8 + jr)*D_ + o] = vv[jr];

  {
    float* qtp = g_Qt + b*D_*S_ + o*S_ + sl + h*8;
    float* ktp = g_Kt + b*D_*S_ + o*S_ + sl + h*8;
    ((float4*)qtp)[0] = make_float4(qv[0],qv[1],qv[2],qv[3]);
    ((float4*)qtp)[1] = make_float4(qv[4],qv[5],qv[6],qv[7]);
    ((float4*)ktp)[0] = make_float4(kv[0],kv[1],kv[2],kv[3]);
    ((float4*)ktp)[1] = make_float4(kv[4],kv[5],kv[6],kv[7]);
  }

  wtot[h][o] = vv[0]+vv[1]+vv[2]+vv[3]+vv[4]+vv[5]+vv[6]+vv[7];

  float red[8];
  #pragma unroll
  for (int jr=0;jr<8;jr++) red[jr] = kv[jr];
  #pragma unroll
  for (int off=16; off>=1; off>>=1){
    #pragma unroll
    for (int jr=0;jr<8;jr++) red[jr] += __shfl_xor_sync(0xffffffffu, red[jr], off);
  }
  int w = t >> 5;
  if ((t & 31) == 0){
    #pragma unroll
    for (int jr=0;jr<8;jr++) wred[w][jr] = red[jr];
  }
  __syncthreads();
  if (t < 16){
    int r = t;
    int hh = r >> 3, jr = r & 7;
    float tot = wred[hh*4+0][jr]+wred[hh*4+1][jr]+wred[hh*4+2][jr]+wred[hh*4+3][jr];
    g_sumK[s0 + r] = 128.f - tot;
  }
  if (t < 128)
    g_totVp[blockIdx.x*128 + t] = wtot[0][t]+wtot[1][t];
}

// ---------------- K2: fused truth + E' + Z + E'@V ------------------------
// 144 blocks x 256 threads (8 warps, 2/SMSP): 128q x 64k tiles, 8q x 4k.
__global__ void __launch_bounds__(256,1) k_main(float* __restrict__ outp){
  extern __shared__ float sm[];
  float* Qts = sm;                 // [128 d][128 q] 16384 fl -> reused as Vs
  float* Kts = sm + 16384;         // [128 d][64 k]   8192 fl -> reused as Es
  float* sKs = sm + 24576;         // [64]
  float* Es  = sm + 16384;         // [64 k][pitch 132] 8448 fl
  float* Vs  = sm;                 // [64 k][128 d]     8192 fl
  int bid = blockIdx.x;
  int t = threadIdx.x;
  float* att = outp + B_*S_*D_;

  int b = bid/72, r = bid - b*72;
  int qt = 0;
  while ((qt+1)*(qt+2) <= r) qt++;
  int k0 = (r - qt*(qt+1))*64;
  int q0 = qt*128;
  int tx = t & 15, ty = t >> 4;    // ty 0..15 (8 q each), tx 0..15 (4 k each)

  const float4* Qg = (const float4*)(g_Qt + b*D_*S_);
  const float4* Kg = (const float4*)(g_Kt + b*D_*S_);
  const float4* Vg = (const float4*)(g_V + b*S_*D_);

  float4* Qts4 = (float4*)Qts;
  float4* Kts4 = (float4*)Kts;

  // stage Q + K + sKs via cp.async
  #pragma unroll
  for (int it=0; it<16; it++){
    int i = t + it*256;                     // 4096 f4
    CP16(su32(&Qts4[i]), &Qg[(i>>5)*256 + (q0>>2) + (i&31)]);
  }
  #pragma unroll
  for (int it=0; it<8; it++){
    int i = t + it*256;                     // 2048 f4
    CP16(su32(&Kts4[i]), &Kg[(i>>4)*256 + (k0>>2) + (i&15)]);
  }
  if (t < 16)
    CP16(su32(&sKs[t*4]), (const float4*)&g_sumK[b*S_ + k0 + t*4]);
  CPC();
  CPW0();
  __syncthreads();

  // phase 1: acc = sum_d [k' <= q'] * k'   (8q x 4k, prefetch d+1)
  float acc[8][4];
  #pragma unroll
  for (int i=0;i<8;i++)
    #pragma unroll
    for (int j=0;j<4;j++) acc[i][j] = 0.f;

  {
    float4 qa0 = Qts4[ty*2],  qa1 = Qts4[ty*2+1];
    float4 kf  = Kts4[tx];
    #pragma unroll 2
    for (int d=0; d<127; d++){
      float4 qn0 = Qts4[(d+1)*32 + ty*2];
      float4 qn1 = Qts4[(d+1)*32 + ty*2 + 1];
      float4 kn  = Kts4[(d+1)*16 + tx];
      p1c84(acc, qa0, qa1, kf);
      qa0=qn0; qa1=qn1; kf=kn;
    }
    p1c84(acc, qa0, qa1, kf);               // d = 127
  }

  // phase 2: T, att store, E' = exp(10T)-1 (overwrites acc), Z partial
  const float inv = 1.f/128.f;
  float sk[4];
  {
    float4 sv = ((const float4*)&sKs[tx*4])[0];
    sk[0]=sv.x; sk[1]=sv.y; sk[2]=sv.z; sk[3]=sv.w;
  }
  #pragma unroll
  for (int i=0;i<8;i++){
    int qg = q0 + ty*8 + i;
    float zrow = 0.f;
    float tt[4];
    #pragma unroll
    for (int j=0;j<4;j++){
      int kg = k0 + tx*4 + j;
      float T = (acc[i][j] + sk[j]) * inv;
      bool val = (kg <= qg);
      T = val ? T : 0.f;
      float ee = val ? (__expf(10.f*T) - 1.f) : 0.f;
      tt[j] = T; acc[i][j] = ee; zrow += ee;
    }
    ((float4*)(att + (b*S_ + qg)*S_ + k0 + tx*4))[0] =
        make_float4(tt[0],tt[1],tt[2],tt[3]);
    // reduce over the 16 tx-lanes (lane bits 0..3)
    #pragma unroll
    for (int off=8; off>=1; off>>=1)
      zrow += __shfl_xor_sync(0xffffffffu, zrow, off);
    if (tx == 0) atomicAdd(&g_Z[b*S_ + qg], zrow);
  }
  __syncthreads();     // all reads of Qts/Kts/sKs done

  // phase 3: V tile via cp.async (latency overlapped with E' staging)
  float4* Vs4 = (float4*)Vs;
  #pragma unroll
  for (int it=0; it<8; it++){
    int i = t + it*256;                     // 2048 f4
    CP16(su32(&Vs4[i]), &Vg[(k0 + (i>>5))*32 + (i&31)]);
  }
  CPC();
  // stage E' (k-major, pitch 132, tx-rotated store order)
  #pragma unroll
  for (int jj=0;jj<4;jj++){
    int j = (jj + tx) & 3;                  // rotation spreads banks
    int kl = tx*4 + j;
    float* ep = Es + kl*132 + ty*8;
    ((float4*)ep)[0] = make_float4(acc[0][j],acc[1][j],acc[2][j],acc[3][j]);
    ((float4*)ep)[1] = make_float4(acc[4][j],acc[5][j],acc[6][j],acc[7][j]);
  }
  CPW0();
  __syncthreads();

  // phase 4: out += E'^T @ V   (8q x 8d per thread, f32x2)
  u64 acc2[8][4];
  #pragma unroll
  for (int i=0;i<8;i++)
    #pragma unroll
    for (int j=0;j<4;j++) acc2[i][j] = 0ull;

  #pragma unroll 2
  for (int k=0;k<64;k++){
    float4 e0 = ((const float4*)&Es[k*132 + ty*8])[0];
    float4 e1 = ((const float4*)&Es[k*132 + ty*8])[1];
    float ev[8] = {e0.x,e0.y,e0.z,e0.w, e1.x,e1.y,e1.z,e1.w};
    float4 v0 = Vs4[k*32 + tx*2];
    float4 v1 = Vs4[k*32 + tx*2 + 1];
    u64 v[4];
    v[0] = pack2(v0.x, v0.y);  v[1] = pack2(v0.z, v0.w);
    v[2] = pack2(v1.x, v1.y);  v[3] = pack2(v1.z, v1.w);
    #pragma unroll
    for (int i=0;i<8;i++){
      u64 e2 = pack2(ev[i], ev[i]);
      #pragma unroll
      for (int j=0;j<4;j++)
        acc2[i][j] = fma2(e2, v[j], acc2[i][j]);
    }
  }

  #pragma unroll
  for (int i=0;i<8;i++){
    int qg = q0 + ty*8 + i;
    float* op = outp + (b*S_ + qg)*D_ + tx*8;
    float a0,a1,a2,a3,a4,a5,a6,a7;
    unpack2(acc2[i][0],a0,a1);
    unpack2(acc2[i][1],a2,a3);
    unpack2(acc2[i][2],a4,a5);
    unpack2(acc2[i][3],a6,a7);
    atomicAdd((float4*)op,       make_float4(a0,a1,a2,a3));
    atomicAdd((float4*)(op + 4), make_float4(a4,a5,a6,a7));
  }
}

// ---------------- K3: out = (out + totV) / (Z + 1024) --------------------
__global__ void __launch_bounds__(256) k_norm(float* __restrict__ outp){
  __shared__ float4 stot[64];
  int t = threadIdx.x;
  {
    int ft = t >> 2, p = t & 3;
    int rb = ft >> 5, col = ft & 31;
    const float4* tp = (const float4*)g_totVp;
    float4 a = make_float4(0.f,0.f,0.f,0.f);
    #pragma unroll 4
    for (int j = p*16; j < p*16+16; j++){
      float4 v = tp[(rb*64 + j)*32 + col];
      a.x+=v.x; a.y+=v.y; a.z+=v.z; a.w+=v.w;
    }
    #pragma unroll
    for (int off=1; off<4; off<<=1){
      a.x += __shfl_xor_sync(0xffffffffu, a.x, off);
      a.y += __shfl_xor_sync(0xffffffffu, a.y, off);
      a.z += __shfl_xor_sync(0xffffffffu, a.z, off);
      a.w += __shfl_xor_sync(0xffffffffu, a.w, off);
    }
    if (p == 0) stot[ft] = a;
  }
  __syncthreads();

  int col = t & 31;
  float4* o4 = (float4*)outp;
  #pragma unroll
  for (int rr=0; rr<2; rr++){
    int row = blockIdx.x*16 + (t>>5) + rr*8;
    float4 v = o4[row*32 + col];
    float4 tv = stot[((row >> 10) << 5) + col];
    float rz = 1.f/(g_Z[row] + 1024.f);
    v.x=(v.x+tv.x)*rz; v.y=(v.y+tv.y)*rz;
    v.z=(v.z+tv.z)*rz; v.w=(v.w+tv.w)*rz;
    o4[row*32 + col] = v;
  }
}

// ---------------- launch ----------------
extern "C" void kernel_launch(void* const* d_in, const int* in_sizes, int n_in,
                              void* d_out, int out_size){
  (void)in_sizes; (void)n_in; (void)out_size;
  const float* x  = (const float*)d_in[0];
  const float* wq = (const float*)d_in[1];
  const float* bq = (const float*)d_in[2];
  const float* wk = (const float*)d_in[3];
  const float* bk = (const float*)d_in[4];
  const float* wv = (const float*)d_in[5];
  const float* bv = (const float*)d_in[6];
  float* out = (float*)d_out;              // (output, attention_truth)

  const int SMQ = (24576 + 2048) * 4;      // 106,496 B
  const int SMM = 24832 * 4;               // 99,328 B
  cudaFuncSetAttribute(k_qkv,  cudaFuncAttributeMaxDynamicSharedMemorySize, SMQ);
  cudaFuncSetAttribute(k_main, cudaFuncAttributeMaxDynamicSharedMemorySize, SMM);

  k_qkv  <<< 128, 256, SMQ >>>(x, wq, bq, wk, bk, wv, bv, out);
  k_main <<< 144, 256, SMM >>>(out);
  k_norm <<< 128, 256 >>>(out);
}